// round 3
// baseline (speedup 1.0000x reference)
#include <cuda_runtime.h>
#include <cstddef>

// Correlation cost volume, B=8 C=96 H=64 W=96, D=21x21, stride2, maxdisp 20.
// out[b, i*21+j, y, x] = scale * sum_c d1[b,c,y,x]*d2[b,c,y+2(i-10),x+2(j-10)]
// scale = s1*s2/(96*out_scale)
//
// Grid: (y=64, b=8, g=3). Each block handles one y row and one group of 7 dy.
// Smem: full d1 row (96 ch x 48 pairs, pad-swizzled) loaded once per block;
//       d2 chunk of 8 channels x 7 rows, double-barriered per chunk.
// Pad-swizzle: pair p at float offset 2p + 2(p>>2)  (conflict-mitigating).

#define NT      256
#define CC      8
#define NCH     12
#define GDY     7
#define TP      4
#define TD      7
#define NXG     12
#define NDXG    3
#define ACTIVE  252
#define NV      10          // TP+TD-1 d2 pairs per thread per channel

#define D1ROW   120         // 48 pairs swizzled -> max 116
#define D2ROW   168         // 68 pairs swizzled -> max 166
#define D1FLOATS (96 * D1ROW)              // 11520
#define D2FLOATS (GDY * CC * D2ROW)        // 9408
#define SMEM_FLOATS (D1FLOATS + D2FLOATS)  // 20928 -> 83712 B

__device__ __forceinline__ unsigned long long ld_u64(const float* p) {
    return *reinterpret_cast<const unsigned long long*>(p);
}

__global__ void __launch_bounds__(NT, 2) corr_kernel(
    const float* __restrict__ d1g, const float* __restrict__ d2g,
    const float* __restrict__ s1, const float* __restrict__ s2,
    const float* __restrict__ osc, float* __restrict__ out)
{
    extern __shared__ float sm[];
    float* sm_d1 = sm;              // [96][D1ROW]
    float* sm_d2 = sm + D1FLOATS;   // [GDY][CC][D2ROW]

    const int y   = blockIdx.x;     // 0..63
    const int b   = blockIdx.y;     // 0..7
    const int g   = blockIdx.z;     // 0..2  (dy group: i = 7g..7g+6)
    const int tid = threadIdx.x;

    // compute mapping
    const int xg  = tid % NXG;
    const int dxg = (tid / NXG) % NDXG;
    const int dyl = tid / (NXG * NDXG);
    const bool act = tid < ACTIVE;
    const int d0  = dxg * TD;

    // loader mapping
    const int lr   = tid >> 5;      // 0..7 (7 == spare)
    const int lane = tid & 31;

    const size_t b96 = (size_t)b * 96;

    // ---- zero-fill d2 buffer once (pads + invalid rows stay zero) ----
    {
        float4 z = make_float4(0.f, 0.f, 0.f, 0.f);
        float4* p = reinterpret_cast<float4*>(sm_d2);
        for (int i = tid; i < D2FLOATS / 4; i += NT) p[i] = z;
    }

    // ---- load full d1 row: 96 channels x 48 pairs (float2), swizzled ----
    {
        const int c8 = tid >> 5;                     // 0..7
        // pair p1 = lane -> floats 2*lane..; pair p2 = lane+32 (lane<16)
        const int s1o = 2 * lane + 2 * (lane >> 2);
        const int p2  = lane + 32;
        const int s2o = 2 * p2 + 2 * (p2 >> 2);
        #pragma unroll
        for (int it = 0; it < 12; ++it) {
            int c = it * 8 + c8;
            const float* gp = d1g + ((b96 + c) * 64 + y) * 96;
            float* srow = sm_d1 + c * D1ROW;
            float2 v1 = reinterpret_cast<const float2*>(gp)[lane];
            *reinterpret_cast<float2*>(srow + s1o) = v1;
            if (lane < 16) {
                float2 v2 = reinterpret_cast<const float2*>(gp)[p2];
                *reinterpret_cast<float2*>(srow + s2o) = v2;
            }
        }
    }

    // ---- precompute d2 loader state (once) ----
    // valid d2 pairs: p in [10,58): x' = 2p-20 in [0,96)
    int   row       = y + 2 * (g * GDY + lr) - 20;
    bool  ldr_valid = (lr < GDY) && ((unsigned)row < 64u);
    const float2* grow0 = reinterpret_cast<const float2*>(
        d2g + (b96 * 64 + (size_t)(ldr_valid ? row : 0)) * 96);
    // slot offsets (floats) within a d2 smem row
    const int pA = 10 + lane, pB = 42 + lane;
    const int sA = 2 * pA + 2 * (pA >> 2);
    const int sB = 2 * pB + 2 * (pB >> 2);
    float* sdst = sm_d2 + lr * (CC * D2ROW);

    // ---- precompute compute-phase smem offsets ----
    int voff[NV];
    {
        const int P0 = 4 * xg + d0;
        #pragma unroll
        for (int k = 0; k < NV; ++k) {
            int P = P0 + k;
            voff[k] = 2 * P + 2 * (P >> 2);
        }
    }
    const int aoff = 10 * xg;

    // ---- accumulators ----
    unsigned long long acc[TP][TD];
    #pragma unroll
    for (int pi = 0; pi < TP; ++pi)
        #pragma unroll
        for (int di = 0; di < TD; ++di) acc[pi][di] = 0ull;

    // ---- main loop over channel chunks ----
    for (int cc = 0; cc < NCH; ++cc) {
        __syncthreads();   // previous chunk's readers done
        if (ldr_valid) {
            const float2* gp = grow0 + (size_t)(cc * CC) * (64 * 96 / 2);
            float* sp = sdst;
            #pragma unroll
            for (int c = 0; c < CC; ++c) {
                float2 vA = gp[lane];
                *reinterpret_cast<float2*>(sp + sA) = vA;
                if (lane < 16) {
                    float2 vB = gp[32 + lane];
                    *reinterpret_cast<float2*>(sp + sB) = vB;
                }
                gp += 64 * 96 / 2;
                sp += D2ROW;
            }
        }
        __syncthreads();

        if (act) {
            const float* arow = sm_d1 + (cc * CC) * D1ROW + aoff;
            const float* vrow = sm_d2 + dyl * (CC * D2ROW);
            #pragma unroll
            for (int c = 0; c < CC; ++c) {
                unsigned long long a[TP];
                #pragma unroll
                for (int pi = 0; pi < TP; ++pi)
                    a[pi] = ld_u64(arow + 2 * pi);
                unsigned long long v[NV];
                #pragma unroll
                for (int k = 0; k < NV; ++k)
                    v[k] = ld_u64(vrow + voff[k]);
                #pragma unroll
                for (int pi = 0; pi < TP; ++pi)
                    #pragma unroll
                    for (int di = 0; di < TD; ++di)
                        asm("fma.rn.f32x2 %0, %1, %2, %0;"
                            : "+l"(acc[pi][di])
                            : "l"(a[pi]), "l"(v[pi + di]));
                arow += D1ROW;
                vrow += D2ROW;
            }
        }
    }

    // ---- epilogue ----
    if (act) {
        float sc = s1[0] * s2[0] / (96.0f * osc[0]);
        int i = g * GDY + dyl;
        #pragma unroll
        for (int pi = 0; pi < TP; ++pi) {
            int x = 2 * (4 * xg + pi);
            #pragma unroll
            for (int di = 0; di < TD; ++di) {
                int j = d0 + di;
                int ch = i * 21 + j;
                unsigned long long u = acc[pi][di];
                float2 r;
                r.x = __uint_as_float((unsigned)(u & 0xffffffffu)) * sc;
                r.y = __uint_as_float((unsigned)(u >> 32)) * sc;
                *reinterpret_cast<float2*>(
                    out + (((size_t)b * 441 + ch) * 64 + y) * 96 + x) = r;
            }
        }
    }
}

extern "C" void kernel_launch(void* const* d_in, const int* in_sizes, int n_in,
                              void* d_out, int out_size) {
    const float* data1     = (const float*)d_in[0];
    const float* data2     = (const float*)d_in[1];
    const float* scale1    = (const float*)d_in[2];
    const float* scale2    = (const float*)d_in[3];
    /* d_in[4] = inter_scale, unused by the reference math */
    const float* out_scale = (const float*)d_in[5];

    size_t smem = SMEM_FLOATS * sizeof(float);
    cudaFuncSetAttribute(corr_kernel,
                         cudaFuncAttributeMaxDynamicSharedMemorySize, (int)smem);

    dim3 grid(64, 8, 3);   // (y, b, dy-group)
    corr_kernel<<<grid, NT, smem>>>(data1, data2, scale1, scale2, out_scale,
                                    (float*)d_out);
}

// round 5
// speedup vs baseline: 1.6083x; 1.6083x over previous
#include <cuda_runtime.h>
#include <cstdint>
#include <cstddef>

// Correlation as band-Gram tf32 mma.sync GEMM (sm_100, legacy HMMA path).
// Per (b, y, par): A[48 x 96] (xp rows), per i: B[n, c] = d2[b,c,y+2i-20,2n-20+par]
// (n in [10,57] real, else 0). out[b, i*21+j, y, 2xp+par] = sc * D[xp, xp+j].

#define NT   192
#define RS   44                 // stage row stride (floats)
#define SWS  748                // stage warp stride (floats)
#define BB   72                 // floats per [par][t'][k] frag block
#define BSM_FLOATS (2*7*12*BB)  // 12096
#define STAGE_OFF  BSM_FLOATS
#define SMEM_FLOATS (BSM_FLOATS + 6*SWS)   // 16584
#define SMEM_BYTES  (SMEM_FLOATS*4)        // 66336

__device__ __forceinline__ uint32_t cvt_tf32(float f) {
    uint32_t r; asm("cvt.rna.tf32.f32 %0, %1;" : "=r"(r) : "f"(f)); return r;
}

__device__ __forceinline__ void mma8(float* c, const uint32_t* a,
                                     uint32_t b0, uint32_t b1) {
    asm volatile(
        "mma.sync.aligned.m16n8k8.row.col.f32.tf32.tf32.f32 "
        "{%0,%1,%2,%3}, {%4,%5,%6,%7}, {%8,%9}, {%0,%1,%2,%3};"
        : "+f"(c[0]), "+f"(c[1]), "+f"(c[2]), "+f"(c[3])
        : "r"(a[0]), "r"(a[1]), "r"(a[2]), "r"(a[3]), "r"(b0), "r"(b1));
}

struct Pref { float4 v1[3], v2[3]; };

// loader unit coords: per warp wp, lane decode (q, hb, xl); u in 0..2.
__device__ __forceinline__ void ldgB(Pref& P, const float* rowp, int h,
                                     int xq, int q, int hb) {
    #pragma unroll
    for (int u = 0; u < 3; ++u) {
        int k = 6*h + 2*u + hb;
        const float* p = rowp + (8*k + q) * 6144 + 4*xq;
        P.v1[u] = *(const float4*)p;
        P.v2[u] = *(const float4*)(p + 4*6144);
    }
}

__device__ __forceinline__ void stsB(const Pref& P, float* bsm, int h,
                                     int xq, int q, int hb) {
    #pragma unroll
    for (int u = 0; u < 3; ++u) {
        int k = 6*h + 2*u + hb;
        const float* a = &P.v1[u].x;
        const float* c4 = &P.v2[u].x;
        #pragma unroll
        for (int e = 0; e < 4; ++e) {
            int par = e & 1;
            int n = 2*xq + 10 + (e >> 1);
            int t = (n >> 3) - 1;                 // 0..6
            int lane2 = ((n & 7) << 2) + q;
            float2 w;
            w.x = __uint_as_float(cvt_tf32(a[e]));
            w.y = __uint_as_float(cvt_tf32(c4[e]));
            *(float2*)(bsm + ((par*7 + t)*12 + k)*BB + lane2*2) = w;
        }
    }
}

__device__ __forceinline__ void comp_half(float (*acc)[4], const uint32_t (*A)[4],
                                          const float* bsm, int par,
                                          int t0, int nt, int kh, int l) {
    #pragma unroll
    for (int kk = 0; kk < 6; ++kk) {
        int k = kh*6 + kk;
        #pragma unroll
        for (int tt = 0; tt < 5; ++tt) {
            if (tt < nt) {
                float2 bv = *(const float2*)(
                    bsm + ((par*7 + t0 + tt)*12 + k)*BB + l*2);
                mma8(acc[tt], A[k],
                     __float_as_uint(bv.x), __float_as_uint(bv.y));
            }
        }
    }
}

__global__ void __launch_bounds__(NT, 2) corr_mma(
    const float* __restrict__ d1, const float* __restrict__ d2,
    const float* __restrict__ s1, const float* __restrict__ s2,
    const float* __restrict__ osc, float* __restrict__ out)
{
    extern __shared__ float sm[];
    float* bsm = sm;
    float* stage = sm + STAGE_OFF;

    const int td = threadIdx.x;
    const int w = td >> 5, l = td & 31;
    const int y = blockIdx.x, b = blockIdx.y;

    const int m = w >> 1, par = w & 1;        // warp role
    const int g = l >> 2, q = l & 3;          // mma lane coords
    // loader lane decode
    const int hb = (l >> 2) & 1;
    const int xl = ((l >> 3) & 1) + 2 * (l >> 4);
    const int xq = 4*w + xl;                  // 0..23

    const int t0 = (m == 0) ? 0 : ((m == 1) ? 1 : 3);
    const int nt = (m == 1) ? 5 : 4;

    // ---- zero smem (B zero-pad slots + stage unwritten cols) ----
    {
        float4 z = make_float4(0.f, 0.f, 0.f, 0.f);
        float4* p = (float4*)sm;
        for (int i = td; i < SMEM_FLOATS/4; i += NT) p[i] = z;
    }

    // ---- load A frags (resident) ----
    uint32_t A[12][4];
    {
        int xa = 2 * (16*m + g) + par;
        const float* p0 = d1 + ((size_t)(b*96)*64 + y) * 96;
        #pragma unroll
        for (int k = 0; k < 12; ++k) {
            const float* pc = p0 + (size_t)(8*k + q) * 6144;
            A[k][0] = cvt_tf32(pc[xa]);
            A[k][1] = cvt_tf32(pc[xa + 16]);
            A[k][2] = cvt_tf32(pc[4*6144 + xa]);
            A[k][3] = cvt_tf32(pc[4*6144 + xa + 16]);
        }
    }

    float acc[5][4];
    #pragma unroll
    for (int tt = 0; tt < 5; ++tt)
        #pragma unroll
        for (int e = 0; e < 4; ++e) acc[tt][e] = 0.f;

    const float sc = s1[0] * s2[0] / (96.0f * osc[0]);
    const float* d2b = d2 + (size_t)b * 589824;
    float* stg = stage + w * SWS;

    // ---- prologue: stage B(0) if valid ----
    __syncthreads();            // zero-fill visible before any STS
    {
        int row0 = y - 20;
        if ((unsigned)row0 < 64u) {
            const float* rowp = d2b + (size_t)row0 * 96;
            Pref P;
            ldgB(P, rowp, 0, xq, q, hb); stsB(P, bsm, 0, xq, q, hb);
            ldgB(P, rowp, 1, xq, q, hb); stsB(P, bsm, 1, xq, q, hb);
        }
    }
    __syncthreads();

    for (int i = 0; i < 21; ++i) {
        const int rowi = y + 2*i - 20;
        const bool vi = (unsigned)rowi < 64u;
        const bool v1 = (i < 20) && ((unsigned)(rowi + 2) < 64u);
        const float* rown = d2b + (size_t)(rowi + 2) * 96;

        Pref P;
        if (v1) ldgB(P, rown, 0, xq, q, hb);
        if (vi) comp_half(acc, A, bsm, par, t0, nt, 0, l);
        __syncthreads();                       // S1

        if (v1) { stsB(P, bsm, 0, xq, q, hb); ldgB(P, rown, 1, xq, q, hb); }
        if (vi) comp_half(acc, A, bsm, par, t0, nt, 1, l);

        if (vi) {
            #pragma unroll
            for (int tt = 0; tt < 5; ++tt) {
                if (tt < nt) {
                    int colb = 8*(t0 + tt + 1) - 16*m;
                    float* s0 = stg + g*RS + colb + 2*q;
                    *(float2*)s0 = make_float2(acc[tt][0], acc[tt][1]);
                    *(float2*)(s0 + 8*RS) = make_float2(acc[tt][2], acc[tt][3]);
                    acc[tt][0] = acc[tt][1] = acc[tt][2] = acc[tt][3] = 0.f;
                }
            }
        }
        __syncthreads();                       // S2

        if (v1) stsB(P, bsm, 1, xq, q, hb);

        // ---- output for i: 21 j x 96 x, coalesced float4 ----
        {
            float* ob = out + ((size_t)(b*441 + i*21)*64 + y) * 96;
            #pragma unroll
            for (int it = 0; it < 3; ++it) {
                int uu = td + NT * it;
                if (uu < 504) {
                    int j = uu / 24, xquad = uu - j*24;
                    float4 o;
                    if (vi) {
                        float v[4];
                        #pragma unroll
                        for (int e = 0; e < 4; ++e) {
                            int x = 4*xquad + e;
                            int pe = x & 1, xp = x >> 1;
                            int mm = xp >> 4, r = xp & 15;
                            v[e] = stage[(2*mm + pe)*SWS + r*RS + r + j] * sc;
                        }
                        o = make_float4(v[0], v[1], v[2], v[3]);
                    } else {
                        o = make_float4(0.f, 0.f, 0.f, 0.f);
                    }
                    *(float4*)(ob + (size_t)j * 6144 + 4*xquad) = o;
                }
            }
        }
    }
}

extern "C" void kernel_launch(void* const* d_in, const int* in_sizes, int n_in,
                              void* d_out, int out_size) {
    const float* data1     = (const float*)d_in[0];
    const float* data2     = (const float*)d_in[1];
    const float* scale1    = (const float*)d_in[2];
    const float* scale2    = (const float*)d_in[3];
    /* d_in[4] = inter_scale, unused by the reference math */
    const float* out_scale = (const float*)d_in[5];

    cudaFuncSetAttribute(corr_mma, cudaFuncAttributeMaxDynamicSharedMemorySize,
                         SMEM_BYTES);
    dim3 grid(64, 8);   // (y, b)
    corr_mma<<<grid, NT, SMEM_BYTES>>>(data1, data2, scale1, scale2, out_scale,
                                       (float*)d_out);
}

// round 6
// speedup vs baseline: 2.7199x; 1.6912x over previous
#include <cuda_runtime.h>
#include <cstdint>
#include <cstddef>

// Correlation as band-Gram tf32 mma.sync GEMM, B pre-formatted to frag layout.
// Pass 1 (reformat): g_B[b][row][par][t][k][64] = tf32 frag blocks of
//   B[n, c] = d2[b, c, row, x'], x' = 2*(8(t+1)+nl) - 20 + par (0 if OOB),
//   block float f = nl*8 + kq*2 + s  <->  lane l=(nl<<2)|kq regs (b0,b1), c=8k+kq+4s.
// Pass 2: per (b,y): A[48x96] per par in regs; per i, 12k x ~4.3t mma.sync
//   m16n8k8 tf32 with B frags LDG'd straight from g_B. Diagonal band out.

#define NT   192
#define RS   44
#define SWS  748                       // per-warp stage stride (floats)
#define STAGE_FLOATS (6 * SWS)         // 4488
#define SMEM_BYTES   (2 * STAGE_FLOATS * 4)   // 35904, double-buffered

#define GB_N 5505024                   // 8*64*2*7*12*64
__device__ uint32_t g_B[GB_N];

__device__ __forceinline__ uint32_t cvt_tf32(float f) {
    uint32_t r; asm("cvt.rna.tf32.f32 %0, %1;" : "=r"(r) : "f"(f)); return r;
}

__device__ __forceinline__ void mma8(float* c, const uint32_t* a,
                                     uint32_t b0, uint32_t b1) {
    asm volatile(
        "mma.sync.aligned.m16n8k8.row.col.f32.tf32.tf32.f32 "
        "{%0,%1,%2,%3}, {%4,%5,%6,%7}, {%8,%9}, {%0,%1,%2,%3};"
        : "+f"(c[0]), "+f"(c[1]), "+f"(c[2]), "+f"(c[3])
        : "r"(a[0]), "r"(a[1]), "r"(a[2]), "r"(a[3]), "r"(b0), "r"(b1));
}

// ---------------- pass 1: reformat d2 -> g_B ----------------
__global__ void __launch_bounds__(256) reformat(const float* __restrict__ d2) {
    int idx = blockIdx.x * 256 + threadIdx.x;
    if (idx >= GB_N) return;
    int f = idx & 63;  int r = idx >> 6;
    int k = r % 12;    r /= 12;
    int t = r % 7;     r /= 7;
    int par = r & 1;   r >>= 1;
    int row = r & 63;  int b = r >> 6;
    int nl = f >> 3, kq = (f >> 1) & 3, s = f & 1;
    int c = 8 * k + kq + 4 * s;
    int x = 2 * (8 * t + 8 + nl) - 20 + par;
    float v = 0.f;
    if ((unsigned)x < 96u)
        v = d2[((b * 96 + c) * 64 + row) * 96 + x];
    g_B[idx] = cvt_tf32(v);
}

// ---------------- pass 2: GEMM ----------------
__global__ void __launch_bounds__(NT, 2) corr_mma(
    const float* __restrict__ d1,
    const float* __restrict__ s1, const float* __restrict__ s2,
    const float* __restrict__ osc, float* __restrict__ out)
{
    extern __shared__ float stage[];   // [2][6][SWS]

    const int td = threadIdx.x;
    const int w = td >> 5, l = td & 31;
    const int y = blockIdx.x, b = blockIdx.y;

    const int m = w >> 1, par = w & 1;
    const int g = l >> 2, q = l & 3;

    const int t0 = (m == 0) ? 0 : ((m == 1) ? 1 : 3);
    const int nt = (m == 1) ? 5 : 4;

    // ---- zero stage buffers (unwritten band cols must read 0) ----
    {
        float4 z = make_float4(0.f, 0.f, 0.f, 0.f);
        float4* p = (float4*)stage;
        for (int i = td; i < 2 * STAGE_FLOATS / 4; i += NT) p[i] = z;
    }

    // ---- load A frags (resident) ----
    uint32_t A[12][4];
    {
        int xa = 2 * (16 * m + g) + par;
        const float* p0 = d1 + ((size_t)(b * 96) * 64 + y) * 96;
        #pragma unroll
        for (int k = 0; k < 12; ++k) {
            const float* pc = p0 + (size_t)(8 * k + q) * 6144;
            A[k][0] = cvt_tf32(pc[xa]);
            A[k][1] = cvt_tf32(pc[xa + 16]);
            A[k][2] = cvt_tf32(pc[4 * 6144 + xa]);
            A[k][3] = cvt_tf32(pc[4 * 6144 + xa + 16]);
        }
    }
    __syncthreads();   // stage zero-fill visible before first stage writes

    float acc[5][4];
    #pragma unroll
    for (int tt = 0; tt < 5; ++tt)
        #pragma unroll
        for (int e = 0; e < 4; ++e) acc[tt][e] = 0.f;

    const float sc = s1[0] * s2[0] / (96.0f * osc[0]);

    for (int i = 0; i < 21; ++i) {
        const int rowi = y + 2 * i - 20;
        const bool vi = (unsigned)rowi < 64u;      // block-uniform
        float* stg = stage + (i & 1) * STAGE_FLOATS + w * SWS;

        if (vi) {
            const uint32_t* base =
                g_B + (size_t)((b * 64 + rowi) * 2 + par) * 5376
                    + t0 * 768 + 2 * l;
            uint2 bufA[5], bufB[5];
            #pragma unroll
            for (int tt = 0; tt < 5; ++tt)
                if (tt < nt)
                    bufA[tt] = *(const uint2*)(base + tt * 768);
            #pragma unroll
            for (int k = 0; k < 12; ++k) {
                uint2* cur = (k & 1) ? bufB : bufA;
                uint2* nxt = (k & 1) ? bufA : bufB;
                if (k < 11) {
                    #pragma unroll
                    for (int tt = 0; tt < 5; ++tt)
                        if (tt < nt)
                            nxt[tt] = *(const uint2*)(base + tt * 768 + (k + 1) * 64);
                }
                #pragma unroll
                for (int tt = 0; tt < 5; ++tt)
                    if (tt < nt)
                        mma8(acc[tt], A[k], cur[tt].x, cur[tt].y);
            }

            // stage accs (transpose to x-major via smem)
            #pragma unroll
            for (int tt = 0; tt < 5; ++tt) {
                if (tt < nt) {
                    int colb = 8 * (t0 + tt + 1) - 16 * m;
                    float* s0 = stg + g * RS + colb + 2 * q;
                    *(float2*)s0 = make_float2(acc[tt][0], acc[tt][1]);
                    *(float2*)(s0 + 8 * RS) = make_float2(acc[tt][2], acc[tt][3]);
                    acc[tt][0] = acc[tt][1] = acc[tt][2] = acc[tt][3] = 0.f;
                }
            }
        }
        __syncthreads();

        // ---- output for i: 21 j x 96 x, coalesced float4 ----
        {
            const float* stb = stage + (i & 1) * STAGE_FLOATS;
            float* ob = out + ((size_t)(b * 441 + i * 21) * 64 + y) * 96;
            #pragma unroll
            for (int it = 0; it < 3; ++it) {
                int uu = td + NT * it;
                if (uu < 504) {
                    int j = uu / 24, xquad = uu - j * 24;
                    float4 o;
                    if (vi) {
                        float v[4];
                        #pragma unroll
                        for (int e = 0; e < 4; ++e) {
                            int x = 4 * xquad + e;
                            int pe = x & 1, xp = x >> 1;
                            int mm = xp >> 4, r = xp & 15;
                            v[e] = stb[(2 * mm + pe) * SWS + r * RS + r + j] * sc;
                        }
                        o = make_float4(v[0], v[1], v[2], v[3]);
                    } else {
                        o = make_float4(0.f, 0.f, 0.f, 0.f);
                    }
                    *(float4*)(ob + (size_t)j * 6144 + 4 * xquad) = o;
                }
            }
        }
    }
}

extern "C" void kernel_launch(void* const* d_in, const int* in_sizes, int n_in,
                              void* d_out, int out_size) {
    const float* data1     = (const float*)d_in[0];
    const float* data2     = (const float*)d_in[1];
    const float* scale1    = (const float*)d_in[2];
    const float* scale2    = (const float*)d_in[3];
    /* d_in[4] = inter_scale, unused by the reference math */
    const float* out_scale = (const float*)d_in[5];

    reformat<<<(GB_N + 255) / 256, 256>>>(data2);

    cudaFuncSetAttribute(corr_mma, cudaFuncAttributeMaxDynamicSharedMemorySize,
                         SMEM_BYTES);
    dim3 grid(64, 8);   // (y, b)
    corr_mma<<<grid, NT, SMEM_BYTES>>>(data1, scale1, scale2, out_scale,
                                       (float*)d_out);
}

// round 7
// speedup vs baseline: 3.3031x; 1.2144x over previous
#include <cuda_runtime.h>
#include <cstdint>
#include <cstddef>

// Correlation as band-Gram tf32 mma.sync GEMM.
// Pass 1: reformat d2 -> g_B frag layout (per (b,row): [par][t][k][64] tf32).
// Pass 2: block = (y-pair, b). Rows y0, y0+2 share B rows: loop s over the 22
//   union rows; warp (h,m,par) computes i = s-h for y = y0+2h. B row staged in
//   smem via cp.async one row ahead; mma operands are conflict-free LDS.64.

#define NT   384
#define RS   44
#define SWS  748
#define STAGE_H 4488                       // 6*SWS floats per y-half
#define B_U32   10752                      // u32 per row (2 par x 5376)
#define B_BYTES 43008
#define BSM_BYTES (2 * B_BYTES)            // 86016
#define STAGE_OFF_B BSM_BYTES
#define SMEM_BYTES (BSM_BYTES + 2 * STAGE_H * 4)   // 121920

#define GB_N 5505024                       // 8*64*10752
__device__ uint32_t g_B[GB_N];

__device__ __forceinline__ uint32_t cvt_tf32(float f) {
    uint32_t r; asm("cvt.rna.tf32.f32 %0, %1;" : "=r"(r) : "f"(f)); return r;
}
__device__ __forceinline__ uint32_t s2u(const void* p) {
    uint32_t a;
    asm("{ .reg .u64 t; cvta.to.shared.u64 t, %1; cvt.u32.u64 %0, t; }"
        : "=r"(a) : "l"(p));
    return a;
}
__device__ __forceinline__ void mma8(float* c, const uint32_t* a,
                                     uint32_t b0, uint32_t b1) {
    asm volatile(
        "mma.sync.aligned.m16n8k8.row.col.f32.tf32.tf32.f32 "
        "{%0,%1,%2,%3}, {%4,%5,%6,%7}, {%8,%9}, {%0,%1,%2,%3};"
        : "+f"(c[0]), "+f"(c[1]), "+f"(c[2]), "+f"(c[3])
        : "r"(a[0]), "r"(a[1]), "r"(a[2]), "r"(a[3]), "r"(b0), "r"(b1));
}

// ---------------- pass 1: reformat d2 -> g_B (smem transpose) --------------
__global__ void __launch_bounds__(256) reformat(const float* __restrict__ d2) {
    __shared__ float t[96 * 100];          // 38.4 KB, row stride 100
    const int td  = threadIdx.x;
    const int row = blockIdx.x & 63;
    const int b   = blockIdx.x >> 6;

    const float* src = d2 + ((size_t)b * 96 * 64 + row) * 96;
    #pragma unroll
    for (int it = 0; it < 9; ++it) {       // 2304 float4 loads
        int lin = it * 256 + td;
        int c = lin / 24, xq = lin - c * 24;
        float4 v = *(const float4*)(src + (size_t)c * 6144 + 4 * xq);
        *(float4*)(t + c * 100 + 4 * xq) = v;
    }
    __syncthreads();

    uint32_t* dst = g_B + (size_t)(b * 64 + row) * B_U32;
    #pragma unroll
    for (int it = 0; it < 42; ++it) {      // 10752 outputs
        int lin = it * 256 + td;
        int f = lin & 63;  int r2 = lin >> 6;
        int k = r2 % 12;   int r3 = r2 / 12;
        int tt = r3 % 7;   int par = r3 / 7;
        int nl = f >> 3, kq = (f >> 1) & 3, s = f & 1;
        int c = 8 * k + kq + 4 * s;
        int x = 16 * tt + 2 * nl - 4 + par;
        float v = ((unsigned)x < 96u) ? t[c * 100 + x] : 0.f;
        dst[lin] = cvt_tf32(v);
    }
}

// ---------------- pass 2: paired-y GEMM ----------------
__device__ __forceinline__ void writeout(
    float* __restrict__ out, const float* __restrict__ stb,
    int b, int yv, int iv, bool vv, float sc, int td)
{
    float* ob = out + ((size_t)(b * 441 + iv * 21) * 64 + yv) * 96;
    #pragma unroll
    for (int rep = 0; rep < 2; ++rep) {
        int uu = td + NT * rep;
        if (uu < 504) {
            int j = uu / 24, xquad = uu - j * 24;
            float4 o;
            if (vv) {
                float v[4];
                #pragma unroll
                for (int e = 0; e < 4; ++e) {
                    int x = 4 * xquad + e;
                    int pe = x & 1, xp = x >> 1;
                    int mm = xp >> 4, rr = xp & 15;
                    v[e] = stb[(2 * mm + pe) * SWS + rr * RS + rr + j] * sc;
                }
                o = make_float4(v[0], v[1], v[2], v[3]);
            } else {
                o = make_float4(0.f, 0.f, 0.f, 0.f);
            }
            *(float4*)(ob + (size_t)j * 6144 + 4 * xquad) = o;
        }
    }
}

__global__ void __launch_bounds__(NT, 1) corr_mma(
    const float* __restrict__ d1,
    const float* __restrict__ s1, const float* __restrict__ s2,
    const float* __restrict__ osc, float* __restrict__ out)
{
    extern __shared__ char smc[];
    uint32_t* bsm = (uint32_t*)smc;                  // [2][2par][5376]
    float* stage = (float*)(smc + STAGE_OFF_B);      // [2h][6][SWS]
    const uint32_t bsm_u = s2u(smc);

    const int td = threadIdx.x;
    const int w = td >> 5, l = td & 31;
    const int h = w / 6, w6 = w % 6, m = w6 >> 1, par = w6 & 1;
    const int g = l >> 2, q = l & 3;
    const int t0 = (m == 0) ? 0 : ((m == 1) ? 1 : 3);
    const int nt = (m == 1) ? 5 : 4;

    const int yp = blockIdx.x;
    const int y0 = 4 * (yp >> 1) + (yp & 1);
    const int b = blockIdx.y;
    const int y = y0 + 2 * h;

    // zero stage
    {
        float4 z = make_float4(0.f, 0.f, 0.f, 0.f);
        float4* p = (float4*)stage;
        for (int i = td; i < 2 * STAGE_H / 4; i += NT) p[i] = z;
    }

    // A frags (register-resident, per warp's y)
    uint32_t A[12][4];
    {
        int xa = 2 * (16 * m + g) + par;
        const float* p0 = d1 + ((size_t)(b * 96) * 64 + y) * 96;
        #pragma unroll
        for (int k = 0; k < 12; ++k) {
            const float* pc = p0 + (size_t)(8 * k + q) * 6144;
            A[k][0] = cvt_tf32(pc[xa]);
            A[k][1] = cvt_tf32(pc[xa + 16]);
            A[k][2] = cvt_tf32(pc[4 * 6144 + xa]);
            A[k][3] = cvt_tf32(pc[4 * 6144 + xa + 16]);
        }
    }

    float acc[5][4];
    #pragma unroll
    for (int tt = 0; tt < 5; ++tt)
        #pragma unroll
        for (int e = 0; e < 4; ++e) acc[tt][e] = 0.f;

    const float sc = s1[0] * s2[0] / (96.0f * osc[0]);
    const size_t gbase = (size_t)(b * 64) * B_U32;

    // prefetch helper: row -> buffer bi (each thread copies 7 x 16B)
    auto prefetch = [&](int row, int bi) {
        if ((unsigned)row < 64u) {
            const char* gp = (const char*)(g_B + gbase + (size_t)row * B_U32)
                             + td * 16;
            uint32_t sa = bsm_u + bi * B_BYTES + td * 16;
            #pragma unroll
            for (int u = 0; u < 7; ++u)
                asm volatile("cp.async.cg.shared.global [%0], [%1], 16;"
                             :: "r"(sa + u * 6144), "l"(gp + u * 6144)
                             : "memory");
        }
        asm volatile("cp.async.commit_group;" ::: "memory");
    };

    prefetch(y0 - 20, 0);

    for (int s = 0; s < 22; ++s) {
        if (s < 21) prefetch(y0 - 20 + 2 * (s + 1), (s + 1) & 1);
        else asm volatile("cp.async.commit_group;" ::: "memory");
        asm volatile("cp.async.wait_group 1;" ::: "memory");
        __syncthreads();

        const int r = y0 + 2 * s - 20;
        const bool vr = (unsigned)r < 64u;
        const int i = s - h;

        if (vr && (unsigned)i < 21u) {
            const uint32_t* bb = bsm + (s & 1) * B_U32 + par * 5376
                                 + t0 * 768 + 2 * l;
            uint2 bufA[5], bufB[5];
            #pragma unroll
            for (int tt = 0; tt < 5; ++tt)
                if (tt < nt) bufA[tt] = *(const uint2*)(bb + tt * 768);
            #pragma unroll
            for (int k = 0; k < 12; ++k) {
                uint2* cur = (k & 1) ? bufB : bufA;
                uint2* nxt = (k & 1) ? bufA : bufB;
                if (k < 11) {
                    #pragma unroll
                    for (int tt = 0; tt < 5; ++tt)
                        if (tt < nt)
                            nxt[tt] = *(const uint2*)(bb + tt * 768 + (k + 1) * 64);
                }
                #pragma unroll
                for (int tt = 0; tt < 5; ++tt)
                    if (tt < nt)
                        mma8(acc[tt], A[k], cur[tt].x, cur[tt].y);
            }
            // stage accs
            float* stg = stage + h * STAGE_H + w6 * SWS;
            #pragma unroll
            for (int tt = 0; tt < 5; ++tt) {
                if (tt < nt) {
                    int colb = 8 * (t0 + tt + 1) - 16 * m;
                    float* s0 = stg + g * RS + colb + 2 * q;
                    *(float2*)s0 = make_float2(acc[tt][0], acc[tt][1]);
                    *(float2*)(s0 + 8 * RS) = make_float2(acc[tt][2], acc[tt][3]);
                    acc[tt][0] = acc[tt][1] = acc[tt][2] = acc[tt][3] = 0.f;
                }
            }
        }
        __syncthreads();

        if (s <= 20) writeout(out, stage,           b, y0,     s,     vr, sc, td);
        if (s >= 1)  writeout(out, stage + STAGE_H, b, y0 + 2, s - 1, vr, sc, td);
    }
}

extern "C" void kernel_launch(void* const* d_in, const int* in_sizes, int n_in,
                              void* d_out, int out_size) {
    const float* data1     = (const float*)d_in[0];
    const float* data2     = (const float*)d_in[1];
    const float* scale1    = (const float*)d_in[2];
    const float* scale2    = (const float*)d_in[3];
    /* d_in[4] = inter_scale, unused by the reference math */
    const float* out_scale = (const float*)d_in[5];

    reformat<<<512, 256>>>(data2);

    cudaFuncSetAttribute(corr_mma, cudaFuncAttributeMaxDynamicSharedMemorySize,
                         SMEM_BYTES);
    dim3 grid(32, 8);   // (y-pair, b)
    corr_mma<<<grid, NT, SMEM_BYTES>>>(data1, scale1, scale2, out_scale,
                                       (float*)d_out);
}

// round 9
// speedup vs baseline: 3.5328x; 1.0696x over previous
#include <cuda_runtime.h>
#include <cstdint>
#include <cstddef>

// Correlation as band-Gram tf32 mma.sync GEMM.
// Pass 1: reformat d2 -> g_B, per (b,row): [par][t][kp:6][lane:32][4] tf32
//   (one LDS.128 per lane per k-pair feeds two m16n8k8 mma's).
// Pass 2: block = (y-pair, b). Rows y0, y0+2 share B rows; loop s over the 23
//   union steps; warp (h,m,par) computes i = s-h. B rows staged via 3-deep
//   cp.async pipeline (prefetch issued AFTER the barrier -> no WAR race);
//   band stage double-buffered -> ONE barrier per s.

#define NT   384
#define SROW 25                            // stage row stride (floats)
#define STAGE_FLOATS (2 * 2 * 48 * SROW)   // 4800 per buffer
#define B_U32   10752                      // u32 per row (2 par x 5376)
#define B_BYTES 43008
#define NBUF    3
#define STAGE_OFF_B (NBUF * B_BYTES)       // 129024
#define SMEM_BYTES (STAGE_OFF_B + 2 * STAGE_FLOATS * 4)   // 167424

#define GB_N 5505024                       // 8*64*10752
__device__ uint32_t g_B[GB_N];

__device__ __forceinline__ uint32_t cvt_tf32(float f) {
    uint32_t r; asm("cvt.rna.tf32.f32 %0, %1;" : "=r"(r) : "f"(f)); return r;
}
__device__ __forceinline__ uint32_t s2u(const void* p) {
    uint32_t a;
    asm("{ .reg .u64 t; cvta.to.shared.u64 t, %1; cvt.u32.u64 %0, t; }"
        : "=r"(a) : "l"(p));
    return a;
}
__device__ __forceinline__ void mma8(float* c, const uint32_t* a,
                                     uint32_t b0, uint32_t b1) {
    asm volatile(
        "mma.sync.aligned.m16n8k8.row.col.f32.tf32.tf32.f32 "
        "{%0,%1,%2,%3}, {%4,%5,%6,%7}, {%8,%9}, {%0,%1,%2,%3};"
        : "+f"(c[0]), "+f"(c[1]), "+f"(c[2]), "+f"(c[3])
        : "r"(a[0]), "r"(a[1]), "r"(a[2]), "r"(a[3]), "r"(b0), "r"(b1));
}

// ---------------- pass 1: reformat d2 -> g_B (smem transpose) --------------
__global__ void __launch_bounds__(256) reformat(const float* __restrict__ d2) {
    __shared__ float t[96 * 100];
    const int td  = threadIdx.x;
    const int row = blockIdx.x & 63;
    const int b   = blockIdx.x >> 6;

    const float* src = d2 + ((size_t)b * 96 * 64 + row) * 96;
    #pragma unroll
    for (int it = 0; it < 9; ++it) {
        int lin = it * 256 + td;
        int c = lin / 24, xq = lin - c * 24;
        float4 v = *(const float4*)(src + (size_t)c * 6144 + 4 * xq);
        *(float4*)(t + c * 100 + 4 * xq) = v;
    }
    __syncthreads();

    uint32_t* dst = g_B + (size_t)(b * 64 + row) * B_U32;
    #pragma unroll
    for (int it = 0; it < 42; ++it) {
        int lin = it * 256 + td;
        int e = lin & 3;
        int l = (lin >> 2) & 31;
        int blk = lin >> 7;                // (par*7 + tt)*6 + kp
        int kp = blk % 6, pt = blk / 6;
        int tt = pt % 7, par = pt / 7;
        int g = l >> 2, q = l & 3;
        int c = 16 * kp + q + 4 * (e & 1) + 8 * (e >> 1);
        int x = 16 * tt + 2 * g - 4 + par;
        float v = ((unsigned)x < 96u) ? t[c * 100 + x] : 0.f;
        dst[lin] = cvt_tf32(v);
    }
}

// ---------------- pass 2: paired-y GEMM, one barrier per step --------------
__device__ __forceinline__ void writeout_half(
    float* __restrict__ out, const float* __restrict__ stb,
    int b, int yv, int iv, bool vv, float sc, int td)
{
    if ((unsigned)iv >= 21u) return;
    float* ob = out + ((size_t)(b * 441 + iv * 21) * 64 + yv) * 96;
    #pragma unroll
    for (int rep = 0; rep < 2; ++rep) {
        int uu = td + NT * rep;
        if (uu < 504) {
            int j = uu / 24, xquad = uu - j * 24;
            float4 o;
            if (vv) {
                float v[4];
                #pragma unroll
                for (int e = 0; e < 4; ++e) {
                    int x = 4 * xquad + e;
                    int pe = x & 1, xp = x >> 1;
                    v[e] = stb[(pe * 48 + xp) * SROW + j] * sc;
                }
                o = make_float4(v[0], v[1], v[2], v[3]);
            } else {
                o = make_float4(0.f, 0.f, 0.f, 0.f);
            }
            __stcs((float4*)(ob + (size_t)j * 6144 + 4 * xquad), o);
        }
    }
}

__global__ void __launch_bounds__(NT, 1) corr_mma(
    const float* __restrict__ d1,
    const float* __restrict__ s1, const float* __restrict__ s2,
    const float* __restrict__ osc, float* __restrict__ out)
{
    extern __shared__ char smc[];
    uint32_t* bsm = (uint32_t*)smc;                  // [3][B_U32]
    float* stage = (float*)(smc + STAGE_OFF_B);      // [2 buf][2h][2par][48][SROW]
    const uint32_t bsm_u = s2u(smc);

    const int td = threadIdx.x;
    const int w = td >> 5, l = td & 31;
    const int h = w / 6, w6 = w % 6, m = w6 >> 1, par = w6 & 1;
    const int g = l >> 2, q = l & 3;
    const int t0 = (m == 0) ? 0 : ((m == 1) ? 1 : 3);
    const int nt = (m == 1) ? 5 : 4;

    const int yp = blockIdx.x;
    const int y0 = 4 * (yp >> 1) + (yp & 1);
    const int b = blockIdx.y;
    const int y = y0 + 2 * h;

    // zero both stage buffers (unwritten band slots must read 0)
    {
        float4 z = make_float4(0.f, 0.f, 0.f, 0.f);
        float4* p = (float4*)stage;
        for (int i = td; i < 2 * STAGE_FLOATS / 4; i += NT) p[i] = z;
    }

    // A frags (register-resident, per warp's y)
    uint32_t A[12][4];
    {
        int xa = 2 * (16 * m + g) + par;
        const float* p0 = d1 + ((size_t)(b * 96) * 64 + y) * 96;
        #pragma unroll
        for (int k = 0; k < 12; ++k) {
            const float* pc = p0 + (size_t)(8 * k + q) * 6144;
            A[k][0] = cvt_tf32(pc[xa]);
            A[k][1] = cvt_tf32(pc[xa + 16]);
            A[k][2] = cvt_tf32(pc[4 * 6144 + xa]);
            A[k][3] = cvt_tf32(pc[4 * 6144 + xa + 16]);
        }
    }

    float acc[5][4];
    #pragma unroll
    for (int tt = 0; tt < 5; ++tt)
        #pragma unroll
        for (int e = 0; e < 4; ++e) acc[tt][e] = 0.f;

    const float sc = s1[0] * s2[0] / (96.0f * osc[0]);
    const size_t gbase = (size_t)(b * 64) * B_U32;

    auto prefetch = [&](int s_idx, int bi) {
        int row = y0 - 20 + 2 * s_idx;
        if (s_idx <= 21 && (unsigned)row < 64u) {
            const char* gp = (const char*)(g_B + gbase + (size_t)row * B_U32)
                             + td * 16;
            uint32_t sa = bsm_u + bi * B_BYTES + td * 16;
            #pragma unroll
            for (int u = 0; u < 7; ++u)
                asm volatile("cp.async.cg.shared.global [%0], [%1], 16;"
                             :: "r"(sa + u * 6144), "l"(gp + u * 6144)
                             : "memory");
        }
        asm volatile("cp.async.commit_group;" ::: "memory");
    };

    prefetch(0, 0);
    prefetch(1, 1);

    for (int s = 0; s < 23; ++s) {
        // P(s) must be complete (P(s+1) may still be in flight)
        asm volatile("cp.async.wait_group 1;" ::: "memory");
        __syncthreads();

        // issue P(s+2) AFTER the barrier: its target buffer (s+2)%3 was last
        // read in compute(s-1), which the barrier above has fully retired.
        prefetch(s + 2, (s + 2) % NBUF);

        // ---- writeout of stage(s-1) from the other stage buffer ----
        if (s >= 1) {
            const float* stb = stage + ((s - 1) & 1) * STAGE_FLOATS;
            bool vp = (unsigned)(y0 + 2 * (s - 1) - 20) < 64u;
            writeout_half(out, stb,                 b, y0,     s - 1, vp, sc, td);
            writeout_half(out, stb + 2 * 48 * SROW, b, y0 + 2, s - 2, vp, sc, td);
        }

        // ---- compute(s) into stage buffer s&1 ----
        const int r = y0 + 2 * s - 20;
        const bool vr = (unsigned)r < 64u;
        const int i = s - h;
        if (s <= 21 && vr && (unsigned)i < 21u) {
            const uint32_t* bb = bsm + (s % NBUF) * B_U32 + par * 5376
                                 + t0 * 768 + 4 * l;
            uint4 bufA[5], bufB[5];
            #pragma unroll
            for (int tt = 0; tt < 5; ++tt)
                if (tt < nt) bufA[tt] = *(const uint4*)(bb + tt * 768);
            #pragma unroll
            for (int kp = 0; kp < 6; ++kp) {
                uint4* cur = (kp & 1) ? bufB : bufA;
                uint4* nxt = (kp & 1) ? bufA : bufB;
                if (kp < 5) {
                    #pragma unroll
                    for (int tt = 0; tt < 5; ++tt)
                        if (tt < nt)
                            nxt[tt] = *(const uint4*)(bb + tt * 768 + (kp + 1) * 128);
                }
                #pragma unroll
                for (int tt = 0; tt < 5; ++tt) {
                    if (tt < nt) {
                        mma8(acc[tt], A[2 * kp],     cur[tt].x, cur[tt].y);
                        mma8(acc[tt], A[2 * kp + 1], cur[tt].z, cur[tt].w);
                    }
                }
            }
            // stage accs (compact band layout, predicated scalar stores)
            float* stg = stage + (s & 1) * STAGE_FLOATS
                         + ((h * 2 + par) * 48 + 16 * m) * SROW;
            #pragma unroll
            for (int tt = 0; tt < 5; ++tt) {
                if (tt < nt) {
                    int col0 = 8 * (t0 + tt + 1) - 16 * m + 2 * q;
                    int r0 = g, r1 = g + 8;
                    int rel0 = col0 - r0, rel1 = col0 - r1;
                    if ((unsigned)rel0 < 25u)       stg[r0 * SROW + rel0]     = acc[tt][0];
                    if ((unsigned)(rel0 + 1) < 25u) stg[r0 * SROW + rel0 + 1] = acc[tt][1];
                    if ((unsigned)rel1 < 25u)       stg[r1 * SROW + rel1]     = acc[tt][2];
                    if ((unsigned)(rel1 + 1) < 25u) stg[r1 * SROW + rel1 + 1] = acc[tt][3];
                    acc[tt][0] = acc[tt][1] = acc[tt][2] = acc[tt][3] = 0.f;
                }
            }
        }
    }
}

extern "C" void kernel_launch(void* const* d_in, const int* in_sizes, int n_in,
                              void* d_out, int out_size) {
    const float* data1     = (const float*)d_in[0];
    const float* data2     = (const float*)d_in[1];
    const float* scale1    = (const float*)d_in[2];
    const float* scale2    = (const float*)d_in[3];
    /* d_in[4] = inter_scale, unused by the reference math */
    const float* out_scale = (const float*)d_in[5];

    reformat<<<512, 256>>>(data2);

    cudaFuncSetAttribute(corr_mma, cudaFuncAttributeMaxDynamicSharedMemorySize,
                         SMEM_BYTES);
    dim3 grid(32, 8);   // (y-pair, b)
    corr_mma<<<grid, NT, SMEM_BYTES>>>(data1, scale1, scale2, out_scale,
                                       (float*)d_out);
}

// round 10
// speedup vs baseline: 5.4627x; 1.5463x over previous
#include <cuda_runtime.h>
#include <cuda_fp16.h>
#include <cstdint>
#include <cstddef>

// Correlation as band-Gram fp16 mma.sync GEMM (m16n8k16, fp32 accumulate).
// Pass 1: reformat d2 -> g_B, per (b,row): [par][t:7][kp:6][lane:32][2 words]
//   word e = half2{ d2[c], d2[c+1] } with c = 16kp + 2q + 8e, x = 16t+2g-4+par.
// Pass 2: block = (y-pair, b), 384 thr, 2 blocks/SM (all 256 blocks resident).
//   Rows y0, y0+2 share B rows; loop s over 23 union steps; warp (h,m,par)
//   computes i = s-h. B rows via cp.async distance-1 double buffer; band stage
//   double-buffered -> one barrier per s.

#define NT   384
#define SROW 25                            // stage row stride (floats)
#define STAGE_FLOATS (2 * 2 * 48 * SROW)   // 4800 per buffer
#define B_U32   5376                       // u32 words per row (2 par x 2688)
#define B_BYTES 21504
#define NBUF    2
#define STAGE_OFF_B (NBUF * B_BYTES)       // 43008
#define SMEM_BYTES (STAGE_OFF_B + 2 * STAGE_FLOATS * 4)   // 81408 -> 2 blk/SM

#define GB_N 2752512                       // 8*64*5376
__device__ uint32_t g_B[GB_N];

__device__ __forceinline__ uint32_t packh2(float a, float b) {
    __half2 h = __floats2half2_rn(a, b);
    return *(uint32_t*)&h;
}
__device__ __forceinline__ uint32_t s2u(const void* p) {
    uint32_t a;
    asm("{ .reg .u64 t; cvta.to.shared.u64 t, %1; cvt.u32.u64 %0, t; }"
        : "=r"(a) : "l"(p));
    return a;
}
__device__ __forceinline__ void mma16(float* c, const uint32_t* a,
                                      uint32_t b0, uint32_t b1) {
    asm volatile(
        "mma.sync.aligned.m16n8k16.row.col.f32.f16.f16.f32 "
        "{%0,%1,%2,%3}, {%4,%5,%6,%7}, {%8,%9}, {%0,%1,%2,%3};"
        : "+f"(c[0]), "+f"(c[1]), "+f"(c[2]), "+f"(c[3])
        : "r"(a[0]), "r"(a[1]), "r"(a[2]), "r"(a[3]), "r"(b0), "r"(b1));
}

// ---------------- pass 1: reformat d2 -> g_B (smem transpose) --------------
__global__ void __launch_bounds__(256) reformat(const float* __restrict__ d2) {
    __shared__ float t[96 * 100];
    const int td  = threadIdx.x;
    const int row = blockIdx.x & 63;
    const int b   = blockIdx.x >> 6;

    const float* src = d2 + ((size_t)b * 96 * 64 + row) * 96;
    #pragma unroll
    for (int it = 0; it < 9; ++it) {
        int lin = it * 256 + td;
        int c = lin / 24, xq = lin - c * 24;
        float4 v = *(const float4*)(src + (size_t)c * 6144 + 4 * xq);
        *(float4*)(t + c * 100 + 4 * xq) = v;
    }
    __syncthreads();

    uint32_t* dst = g_B + (size_t)(b * 64 + row) * B_U32;
    #pragma unroll
    for (int it = 0; it < 21; ++it) {      // 5376 words
        int lin = it * 256 + td;
        int e = lin & 1;
        int l = (lin >> 1) & 31;
        int blk = lin >> 6;                // (par*7 + tt)*6 + kp
        int kp = blk % 6, pt = blk / 6;
        int tt = pt % 7, par = pt / 7;
        int g = l >> 2, q = l & 3;
        int c = 16 * kp + 2 * q + 8 * e;
        int x = 16 * tt + 2 * g - 4 + par;
        float v0 = 0.f, v1 = 0.f;
        if ((unsigned)x < 96u) { v0 = t[c * 100 + x]; v1 = t[(c + 1) * 100 + x]; }
        dst[lin] = packh2(v0, v1);
    }
}

// ---------------- pass 2: paired-y GEMM ----------------
__device__ __forceinline__ void writeout_half(
    float* __restrict__ out, const float* __restrict__ stb,
    int b, int yv, int iv, bool vv, float sc, int td)
{
    if ((unsigned)iv >= 21u) return;
    float* ob = out + ((size_t)(b * 441 + iv * 21) * 64 + yv) * 96;
    #pragma unroll
    for (int rep = 0; rep < 2; ++rep) {
        int uu = td + NT * rep;
        if (uu < 504) {
            int j = uu / 24, xquad = uu - j * 24;
            float4 o;
            if (vv) {
                float v[4];
                #pragma unroll
                for (int e = 0; e < 4; ++e) {
                    int x = 4 * xquad + e;
                    int pe = x & 1, xp = x >> 1;
                    v[e] = stb[(pe * 48 + xp) * SROW + j] * sc;
                }
                o = make_float4(v[0], v[1], v[2], v[3]);
            } else {
                o = make_float4(0.f, 0.f, 0.f, 0.f);
            }
            __stcs((float4*)(ob + (size_t)j * 6144 + 4 * xquad), o);
        }
    }
}

__global__ void __launch_bounds__(NT, 2) corr_mma(
    const float* __restrict__ d1,
    const float* __restrict__ s1, const float* __restrict__ s2,
    const float* __restrict__ osc, float* __restrict__ out)
{
    extern __shared__ char smc[];
    uint32_t* bsm = (uint32_t*)smc;                  // [2][B_U32]
    float* stage = (float*)(smc + STAGE_OFF_B);      // [2 buf][2h][2par][48][SROW]
    const uint32_t bsm_u = s2u(smc);

    const int td = threadIdx.x;
    const int w = td >> 5, l = td & 31;
    const int h = w / 6, w6 = w % 6, m = w6 >> 1, par = w6 & 1;
    const int g = l >> 2, q = l & 3;
    const int t0 = (m == 0) ? 0 : ((m == 1) ? 1 : 3);
    const int nt = (m == 1) ? 5 : 4;

    const int yp = blockIdx.x;
    const int y0 = 4 * (yp >> 1) + (yp & 1);
    const int b = blockIdx.y;
    const int y = y0 + 2 * h;

    // zero both stage buffers
    {
        float4 z = make_float4(0.f, 0.f, 0.f, 0.f);
        float4* p = (float4*)stage;
        for (int i = td; i < 2 * STAGE_FLOATS / 4; i += NT) p[i] = z;
    }

    // A frags (fp16, register-resident, per warp's y)
    uint32_t A[6][4];
    {
        int xg = 2 * (16 * m + g) + par;
        int xg8 = xg + 16;
        const float* p0 = d1 + ((size_t)(b * 96) * 64 + y) * 96;
        #pragma unroll
        for (int kp = 0; kp < 6; ++kp) {
            const float* pc = p0 + (size_t)(16 * kp + 2 * q) * 6144;
            A[kp][0] = packh2(pc[xg],             pc[6144 + xg]);
            A[kp][1] = packh2(pc[xg8],            pc[6144 + xg8]);
            A[kp][2] = packh2(pc[8 * 6144 + xg],  pc[9 * 6144 + xg]);
            A[kp][3] = packh2(pc[8 * 6144 + xg8], pc[9 * 6144 + xg8]);
        }
    }

    float acc[5][4];
    #pragma unroll
    for (int tt = 0; tt < 5; ++tt)
        #pragma unroll
        for (int e = 0; e < 4; ++e) acc[tt][e] = 0.f;

    const float sc = s1[0] * s2[0] / (96.0f * osc[0]);
    const size_t gbase = (size_t)(b * 64) * B_U32;

    auto prefetch = [&](int s_idx, int bi) {
        int row = y0 - 20 + 2 * s_idx;
        if (s_idx <= 21 && (unsigned)row < 64u) {
            const char* gp = (const char*)(g_B + gbase + (size_t)row * B_U32);
            uint32_t sa = bsm_u + bi * B_BYTES;
            #pragma unroll
            for (int u = 0; u < 4; ++u) {
                int idx = u * NT + td;
                if (idx < 1344)
                    asm volatile("cp.async.cg.shared.global [%0], [%1], 16;"
                                 :: "r"(sa + idx * 16), "l"(gp + idx * 16)
                                 : "memory");
            }
        }
        asm volatile("cp.async.commit_group;" ::: "memory");
    };

    prefetch(0, 0);

    for (int s = 0; s < 23; ++s) {
        asm volatile("cp.async.wait_group 0;" ::: "memory");
        __syncthreads();

        // P(s+1) into buffer (s+1)&1: last read in compute(s-1), retired above.
        prefetch(s + 1, (s + 1) & 1);

        // ---- writeout of stage(s-1) from the other stage buffer ----
        if (s >= 1) {
            const float* stb = stage + ((s - 1) & 1) * STAGE_FLOATS;
            bool vp = (unsigned)(y0 + 2 * (s - 1) - 20) < 64u;
            writeout_half(out, stb,                 b, y0,     s - 1, vp, sc, td);
            writeout_half(out, stb + 2 * 48 * SROW, b, y0 + 2, s - 2, vp, sc, td);
        }

        // ---- compute(s) into stage buffer s&1 ----
        const int r = y0 + 2 * s - 20;
        const bool vr = (unsigned)r < 64u;
        const int i = s - h;
        if (s <= 21 && vr && (unsigned)i < 21u) {
            const uint32_t* bb = bsm + (s & 1) * B_U32 + par * 2688
                                 + t0 * 384 + 2 * l;
            #pragma unroll
            for (int kp = 0; kp < 6; ++kp) {
                uint2 bv[5];
                #pragma unroll
                for (int tt = 0; tt < 5; ++tt)
                    if (tt < nt)
                        bv[tt] = *(const uint2*)(bb + tt * 384 + kp * 64);
                #pragma unroll
                for (int tt = 0; tt < 5; ++tt)
                    if (tt < nt)
                        mma16(acc[tt], A[kp], bv[tt].x, bv[tt].y);
            }
            // stage accs (compact band layout, predicated scalar stores)
            float* stg = stage + (s & 1) * STAGE_FLOATS
                         + ((h * 2 + par) * 48 + 16 * m) * SROW;
            #pragma unroll
            for (int tt = 0; tt < 5; ++tt) {
                if (tt < nt) {
                    int col0 = 8 * (t0 + tt + 1) - 16 * m + 2 * q;
                    int r0 = g, r1 = g + 8;
                    int rel0 = col0 - r0, rel1 = col0 - r1;
                    if ((unsigned)rel0 < 25u)       stg[r0 * SROW + rel0]     = acc[tt][0];
                    if ((unsigned)(rel0 + 1) < 25u) stg[r0 * SROW + rel0 + 1] = acc[tt][1];
                    if ((unsigned)rel1 < 25u)       stg[r1 * SROW + rel1]     = acc[tt][2];
                    if ((unsigned)(rel1 + 1) < 25u) stg[r1 * SROW + rel1 + 1] = acc[tt][3];
                    acc[tt][0] = acc[tt][1] = acc[tt][2] = acc[tt][3] = 0.f;
                }
            }
        }
    }
}

extern "C" void kernel_launch(void* const* d_in, const int* in_sizes, int n_in,
                              void* d_out, int out_size) {
    const float* data1     = (const float*)d_in[0];
    const float* data2     = (const float*)d_in[1];
    const float* scale1    = (const float*)d_in[2];
    const float* scale2    = (const float*)d_in[3];
    /* d_in[4] = inter_scale, unused by the reference math */
    const float* out_scale = (const float*)d_in[5];

    reformat<<<512, 256>>>(data2);

    cudaFuncSetAttribute(corr_mma, cudaFuncAttributeMaxDynamicSharedMemorySize,
                         SMEM_BYTES);
    dim3 grid(32, 8);   // (y-pair, b)
    corr_mma<<<grid, NT, SMEM_BYTES>>>(data1, scale1, scale2, out_scale,
                                       (float*)d_out);
}